// round 1
// baseline (speedup 1.0000x reference)
#include <cuda_runtime.h>

// Shapes (fixed by the problem)
#define BATCH 32
#define CIN   1024      // input / output channels
#define PMID  256       // mid channels (P1 = P2)
#define HH    28
#define WW    28
#define HW    784       // 28*28
#define HWP   900       // padded 30*30

// Scratch (allocation-free rule: __device__ globals)
__device__ float g_y1 [BATCH * PMID * HW];   // conv1 output (pre-shuffle)
__device__ float g_y1p[BATCH * PMID * HWP];  // shuffled + zero-padded (30x30)
__device__ float g_y2 [BATCH * PMID * HW];   // conv3x3 output

// ---------------------------------------------------------------------------
// K1: y1 = relu(w1 @ x) per batch.  M=256, K=1024, N=784.
// BM=BN=64, BK=16, 256 threads, 4x4 microtile.
// ---------------------------------------------------------------------------
__global__ __launch_bounds__(256) void k_conv1(const float* __restrict__ x,
                                               const float* __restrict__ w1) {
    const int b  = blockIdx.z;
    const int m0 = blockIdx.y * 64;
    const int n0 = blockIdx.x * 64;

    __shared__ float As[16][68];  // [k][m], padded
    __shared__ float Bs[16][64];  // [k][n]

    const int tid = threadIdx.x;
    const int tx = tid & 15, ty = tid >> 4;
    const int a_row = tid >> 2, a_col = (tid & 3) << 2;   // A: 64 rows x 16 k
    const int b_row = tid >> 4, b_col = (tid & 15) << 2;  // B: 16 k x 64 n

    const float* xb = x + (size_t)b * CIN * HW;
    float acc[4][4] = {};

    for (int k0 = 0; k0 < CIN; k0 += 16) {
        float4 av = *(const float4*)(w1 + (size_t)(m0 + a_row) * CIN + k0 + a_col);
        As[a_col + 0][a_row] = av.x;
        As[a_col + 1][a_row] = av.y;
        As[a_col + 2][a_row] = av.z;
        As[a_col + 3][a_row] = av.w;

        float4 bv = make_float4(0.f, 0.f, 0.f, 0.f);
        if (n0 + b_col < HW)
            bv = *(const float4*)(xb + (size_t)(k0 + b_row) * HW + n0 + b_col);
        *(float4*)&Bs[b_row][b_col] = bv;
        __syncthreads();

        #pragma unroll
        for (int k = 0; k < 16; k++) {
            float4 a  = *(const float4*)&As[k][ty << 2];
            float4 bb = *(const float4*)&Bs[k][tx << 2];
            float ar[4] = {a.x, a.y, a.z, a.w};
            float br[4] = {bb.x, bb.y, bb.z, bb.w};
            #pragma unroll
            for (int i = 0; i < 4; i++)
                #pragma unroll
                for (int j = 0; j < 4; j++)
                    acc[i][j] += ar[i] * br[j];
        }
        __syncthreads();
    }

    #pragma unroll
    for (int i = 0; i < 4; i++) {
        int m = m0 + (ty << 2) + i;
        float* dst = g_y1 + (size_t)(b * PMID + m) * HW;
        #pragma unroll
        for (int j = 0; j < 4; j++) {
            int n = n0 + (tx << 2) + j;
            if (n < HW) dst[n] = fmaxf(acc[i][j], 0.f);
        }
    }
}

// ---------------------------------------------------------------------------
// K2: per-channel spatial shuffle of y1, written into zero-padded 30x30 layout.
// One block per (b, p) row.
// ---------------------------------------------------------------------------
__global__ __launch_bounds__(256) void k_shuffle_pad(const int* __restrict__ perm) {
    const int bp = blockIdx.x;          // 0 .. 32*256-1
    const int p  = bp & (PMID - 1);
    const float* src = g_y1 + (size_t)bp * HW;
    float* dst       = g_y1p + (size_t)bp * HWP;
    const int* pr    = perm + (size_t)p * HW;

    for (int t = threadIdx.x; t < HWP; t += 256) {
        int h = t / 30, w = t % 30;
        float v = 0.f;
        if (h >= 1 && h <= HH && w >= 1 && w <= WW)
            v = src[pr[(h - 1) * WW + (w - 1)]];
        dst[t] = v;
    }
}

// ---------------------------------------------------------------------------
// K3: y2 = relu(conv3x3(y1p, wd)).  Implicit GEMM: M=256 (q), N=784, K=256*9.
// Block: 64 q x 64 hw columns, channel chunks of 8, halo tile in smem.
// ---------------------------------------------------------------------------
#define CHUNK 8
__global__ __launch_bounds__(256) void k_conv3(const float* __restrict__ wd) {
    const int b   = blockIdx.z;
    const int q0  = blockIdx.y * 64;
    const int hw0 = blockIdx.x * 64;
    const int r0  = hw0 / WW;   // first padded row needed

    __shared__ float Aw[CHUNK][9][68];   // [p][tap][q], padded
    __shared__ float Bh[CHUNK][184];     // halo: up to 6 padded rows x 30

    const int tid = threadIdx.x;
    const int tx = tid & 15, ty = tid >> 4;

    int  off[4];
    bool valid[4];
    #pragma unroll
    for (int j = 0; j < 4; j++) {
        int hw = hw0 + (tx << 2) + j;
        valid[j] = (hw < HW);
        int hwc = valid[j] ? hw : (HW - 1);
        off[j] = (hwc / WW - r0) * 30 + (hwc % WW);   // top-left of 3x3 window
    }

    const float* y1pb = g_y1p + (size_t)b * PMID * HWP;
    float acc[4][4] = {};

    for (int pc = 0; pc < PMID; pc += CHUNK) {
        // Load weights: 64 q x CHUNK p x 9 taps = 4608 floats
        float* awf = &Aw[0][0][0];
        #pragma unroll
        for (int i = 0; i < 18; i++) {
            int e   = tid + i * 256;
            int ql  = e / 72;
            int l72 = e - ql * 72;   // pl*9 + tap
            awf[l72 * 68 + ql] =
                wd[(size_t)(q0 + ql) * (PMID * 9) + (size_t)pc * 9 + l72];
        }
        // Load input halo
        for (int t = tid; t < CHUNK * 184; t += 256) {
            int pl = t / 184, tt = t - pl * 184;
            int gi = r0 * 30 + tt;
            float v = 0.f;
            if (tt < 180 && gi < HWP)
                v = y1pb[(size_t)(pc + pl) * HWP + gi];
            Bh[pl][tt] = v;
        }
        __syncthreads();

        #pragma unroll
        for (int pl = 0; pl < CHUNK; pl++) {
            #pragma unroll
            for (int tap = 0; tap < 9; tap++) {
                const int dy = tap / 3, dx = tap % 3;
                const int toff = dy * 30 + dx;
                float4 aq = *(const float4*)&Aw[pl][tap][ty << 2];
                float ar[4] = {aq.x, aq.y, aq.z, aq.w};
                #pragma unroll
                for (int j = 0; j < 4; j++) {
                    float bv = Bh[pl][off[j] + toff];
                    #pragma unroll
                    for (int i = 0; i < 4; i++)
                        acc[i][j] += ar[i] * bv;
                }
            }
        }
        __syncthreads();
    }

    #pragma unroll
    for (int i = 0; i < 4; i++) {
        int q = q0 + (ty << 2) + i;
        float* dst = g_y2 + (size_t)(b * PMID + q) * HW;
        #pragma unroll
        for (int j = 0; j < 4; j++) {
            int n = hw0 + (tx << 2) + j;
            if (valid[j]) dst[n] = fmaxf(acc[i][j], 0.f);
        }
    }
}

// ---------------------------------------------------------------------------
// K4: out = relu(w3 @ y2 + shuffled residual).  M=1024, K=256, N=784.
// ---------------------------------------------------------------------------
__global__ __launch_bounds__(256) void k_conv1b(const float* __restrict__ w3,
                                                const float* __restrict__ x,
                                                const int* __restrict__ perm_res,
                                                float* __restrict__ out) {
    const int b  = blockIdx.z;
    const int m0 = blockIdx.y * 64;
    const int n0 = blockIdx.x * 64;

    __shared__ float As[16][68];
    __shared__ float Bs[16][64];

    const int tid = threadIdx.x;
    const int tx = tid & 15, ty = tid >> 4;
    const int a_row = tid >> 2, a_col = (tid & 3) << 2;
    const int b_row = tid >> 4, b_col = (tid & 15) << 2;

    const float* y2b = g_y2 + (size_t)b * PMID * HW;
    float acc[4][4] = {};

    for (int k0 = 0; k0 < PMID; k0 += 16) {
        float4 av = *(const float4*)(w3 + (size_t)(m0 + a_row) * PMID + k0 + a_col);
        As[a_col + 0][a_row] = av.x;
        As[a_col + 1][a_row] = av.y;
        As[a_col + 2][a_row] = av.z;
        As[a_col + 3][a_row] = av.w;

        float4 bv = make_float4(0.f, 0.f, 0.f, 0.f);
        if (n0 + b_col < HW)
            bv = *(const float4*)(y2b + (size_t)(k0 + b_row) * HW + n0 + b_col);
        *(float4*)&Bs[b_row][b_col] = bv;
        __syncthreads();

        #pragma unroll
        for (int k = 0; k < 16; k++) {
            float4 a  = *(const float4*)&As[k][ty << 2];
            float4 bb = *(const float4*)&Bs[k][tx << 2];
            float ar[4] = {a.x, a.y, a.z, a.w};
            float br[4] = {bb.x, bb.y, bb.z, bb.w};
            #pragma unroll
            for (int i = 0; i < 4; i++)
                #pragma unroll
                for (int j = 0; j < 4; j++)
                    acc[i][j] += ar[i] * br[j];
        }
        __syncthreads();
    }

    #pragma unroll
    for (int i = 0; i < 4; i++) {
        int m = m0 + (ty << 2) + i;
        const int*   pr  = perm_res + (size_t)m * HW;
        const float* xr  = x  + (size_t)(b * CIN + m) * HW;
        float*       dst = out + (size_t)(b * CIN + m) * HW;
        #pragma unroll
        for (int j = 0; j < 4; j++) {
            int n = n0 + (tx << 2) + j;
            if (n < HW) {
                float r = xr[pr[n]];
                dst[n] = fmaxf(acc[i][j] + r, 0.f);
            }
        }
    }
}

// ---------------------------------------------------------------------------
// Launch
// ---------------------------------------------------------------------------
extern "C" void kernel_launch(void* const* d_in, const int* in_sizes, int n_in,
                              void* d_out, int out_size) {
    const float* x        = (const float*)d_in[0];
    const float* w1       = (const float*)d_in[1];
    const float* wd       = (const float*)d_in[2];
    const float* w3       = (const float*)d_in[3];
    const int*   perm_d   = (const int*)d_in[4];
    const int*   perm_res = (const int*)d_in[5];
    float* out = (float*)d_out;

    (void)in_sizes; (void)n_in; (void)out_size;

    // N tiles of 64 over 784 -> 13 (last partial)
    k_conv1   <<<dim3(13, 4, BATCH), 256>>>(x, w1);
    k_shuffle_pad<<<BATCH * PMID, 256>>>(perm_d);
    k_conv3   <<<dim3(13, 4, BATCH), 256>>>(wd);
    k_conv1b  <<<dim3(13, 16, BATCH), 256>>>(w3, x, perm_res, out);
}

// round 2
// speedup vs baseline: 1.2225x; 1.2225x over previous
#include <cuda_runtime.h>

#define BATCH 32
#define CIN   1024
#define PMID  256
#define HH    28
#define WW    28
#define HW    784
#define HWP   900      // 30*30

// Scratch (__device__ globals; no allocations allowed)
__device__ float g_y1 [BATCH * PMID * HW];
__device__ float g_y1p[BATCH * PMID * HWP];
__device__ float g_y2 [BATCH * PMID * HW];

// ---------------------------------------------------------------------------
// GEMM kernel (conv1): y1 = relu(w1 @ x).  M=256, K=1024, N=784 per batch.
// Tile 128(M) x 112(N), BK=8, 256 threads, 8x7 microtile. Exact N tiling.
// ---------------------------------------------------------------------------
__global__ __launch_bounds__(256) void k_conv1(const float* __restrict__ x,
                                               const float* __restrict__ w1) {
    const int b  = blockIdx.z;
    const int m0 = blockIdx.y * 128;
    const int n0 = blockIdx.x * 112;

    __shared__ float As[8][132];   // [k][m]
    __shared__ float Bs[8][112];   // [k][n]

    const int tid = threadIdx.x;
    const int tx = tid & 15, ty = tid >> 4;

    const float* xb = x + (size_t)b * CIN * HW;

    // A load mapping: m = tid/2, kc = (tid%2)*4
    const int am = tid >> 1, akc = (tid & 1) << 2;
    // B load mapping: threads 0..223: k = t/28, c4 = (t%28)*4
    const bool bAct = tid < 224;
    const int bk = tid / 28, bc4 = (tid % 28) << 2;

    float4 aR = *(const float4*)(w1 + (size_t)(m0 + am) * CIN + akc);
    float4 bR;
    if (bAct) bR = *(const float4*)(xb + (size_t)bk * HW + n0 + bc4);

    float acc[8][7] = {};

    for (int k0 = 0; k0 < CIN; k0 += 8) {
        As[akc + 0][am] = aR.x;
        As[akc + 1][am] = aR.y;
        As[akc + 2][am] = aR.z;
        As[akc + 3][am] = aR.w;
        if (bAct) *(float4*)&Bs[bk][bc4] = bR;
        __syncthreads();

        if (k0 + 8 < CIN) {
            aR = *(const float4*)(w1 + (size_t)(m0 + am) * CIN + k0 + 8 + akc);
            if (bAct) bR = *(const float4*)(xb + (size_t)(bk + k0 + 8) * HW + n0 + bc4);
        }

        #pragma unroll
        for (int k = 0; k < 8; k++) {
            float4 a0 = *(const float4*)&As[k][ty << 3];
            float4 a1 = *(const float4*)&As[k][(ty << 3) + 4];
            float ar[8] = {a0.x, a0.y, a0.z, a0.w, a1.x, a1.y, a1.z, a1.w};
            float br[7];
            #pragma unroll
            for (int j = 0; j < 7; j++) br[j] = Bs[k][tx * 7 + j];
            #pragma unroll
            for (int i = 0; i < 8; i++)
                #pragma unroll
                for (int j = 0; j < 7; j++)
                    acc[i][j] += ar[i] * br[j];
        }
        __syncthreads();
    }

    #pragma unroll
    for (int i = 0; i < 8; i++) {
        int m = m0 + (ty << 3) + i;
        float* dst = g_y1 + (size_t)(b * PMID + m) * HW + n0 + tx * 7;
        #pragma unroll
        for (int j = 0; j < 7; j++) dst[j] = fmaxf(acc[i][j], 0.f);
    }
}

// ---------------------------------------------------------------------------
// K2: shuffle + zero-pad y1 -> y1p (30x30)
// ---------------------------------------------------------------------------
__global__ __launch_bounds__(256) void k_shuffle_pad(const int* __restrict__ perm) {
    const int bp = blockIdx.x;
    const int p  = bp & (PMID - 1);
    const float* src = g_y1 + (size_t)bp * HW;
    float* dst       = g_y1p + (size_t)bp * HWP;
    const int* pr    = perm + (size_t)p * HW;

    for (int t = threadIdx.x; t < HWP; t += 256) {
        int h = t / 30, w = t % 30;
        float v = 0.f;
        if (h >= 1 && h <= HH && w >= 1 && w <= WW)
            v = src[pr[(h - 1) * WW + (w - 1)]];
        dst[t] = v;
    }
}

// ---------------------------------------------------------------------------
// K3: y2 = relu(conv3x3(y1p, wd)). Tile 128(q) x 112(hw) = 4 full rows of 28.
// Per-thread: 8 q x 7 cols, all 7 cols in ONE spatial row -> 3x9 reg window.
// Channel chunk = 8.
// ---------------------------------------------------------------------------
#define CH3 8
__global__ __launch_bounds__(256) void k_conv3(const float* __restrict__ wd) {
    const int b  = blockIdx.z;
    const int q0 = blockIdx.y * 128;
    const int bx = blockIdx.x;          // spatial tile: out rows 4*bx..4*bx+3

    __shared__ float Aw[CH3 * 9][132];  // [pl*9+tap][q]
    __shared__ float Bh[CH3][184];      // 6 padded rows x 30 per channel

    const int tid = threadIdx.x;
    const int tx = tid & 15, ty = tid >> 4;
    const int rloc = tx >> 2;           // local out row 0..3
    const int c0   = (tx & 3) * 7;      // start col within row (0,7,14,21)

    const float* y1pb = g_y1p + (size_t)b * PMID * HWP;
    float acc[8][7] = {};

    for (int pc = 0; pc < PMID; pc += CH3) {
        // weights: 128 q * 72 (pl,tap) ; wd row-major [q][p][3][3]
        #pragma unroll
        for (int i = 0; i < 36; i++) {
            int e   = tid + i * 256;
            int ql  = e / 72;
            int l72 = e - ql * 72;
            Aw[l72][ql] = wd[(size_t)(q0 + ql) * (PMID * 9) + (size_t)pc * 9 + l72];
        }
        // halo: 8 channels x 180 floats (rows 4bx..4bx+5 of padded 30x30)
        for (int t = tid; t < CH3 * 45; t += 256) {
            int pl = t / 45, i4 = (t - pl * 45) << 2;
            float4 v = *(const float4*)(y1pb + (size_t)(pc + pl) * HWP + bx * 120 + i4);
            *(float4*)&Bh[pl][i4] = v;
        }
        __syncthreads();

        #pragma unroll
        for (int pl = 0; pl < CH3; pl++) {
            float win[3][9];
            #pragma unroll
            for (int dy = 0; dy < 3; dy++)
                #pragma unroll
                for (int e = 0; e < 9; e++)
                    win[dy][e] = Bh[pl][(rloc + dy) * 30 + c0 + e];

            #pragma unroll
            for (int tap = 0; tap < 9; tap++) {
                const int dy = tap / 3, dx = tap % 3;
                float4 a0 = *(const float4*)&Aw[pl * 9 + tap][ty << 3];
                float4 a1 = *(const float4*)&Aw[pl * 9 + tap][(ty << 3) + 4];
                float ar[8] = {a0.x, a0.y, a0.z, a0.w, a1.x, a1.y, a1.z, a1.w};
                #pragma unroll
                for (int i = 0; i < 8; i++)
                    #pragma unroll
                    for (int j = 0; j < 7; j++)
                        acc[i][j] += ar[i] * win[dy][dx + j];
            }
        }
        __syncthreads();
    }

    const int hwbase = bx * 112 + rloc * 28 + c0;
    #pragma unroll
    for (int i = 0; i < 8; i++) {
        int q = q0 + (ty << 3) + i;
        float* dst = g_y2 + (size_t)(b * PMID + q) * HW + hwbase;
        #pragma unroll
        for (int j = 0; j < 7; j++) dst[j] = fmaxf(acc[i][j], 0.f);
    }
}

// ---------------------------------------------------------------------------
// K4: out = relu(w3 @ y2 + shuffled residual). M=1024, K=256, N=784.
// ---------------------------------------------------------------------------
__global__ __launch_bounds__(256) void k_conv1b(const float* __restrict__ w3,
                                                const float* __restrict__ x,
                                                const int* __restrict__ perm_res,
                                                float* __restrict__ out) {
    const int b  = blockIdx.z;
    const int m0 = blockIdx.y * 128;
    const int n0 = blockIdx.x * 112;

    __shared__ float As[8][132];
    __shared__ float Bs[8][112];

    const int tid = threadIdx.x;
    const int tx = tid & 15, ty = tid >> 4;

    const float* y2b = g_y2 + (size_t)b * PMID * HW;

    const int am = tid >> 1, akc = (tid & 1) << 2;
    const bool bAct = tid < 224;
    const int bk = tid / 28, bc4 = (tid % 28) << 2;

    float4 aR = *(const float4*)(w3 + (size_t)(m0 + am) * PMID + akc);
    float4 bR;
    if (bAct) bR = *(const float4*)(y2b + (size_t)bk * HW + n0 + bc4);

    float acc[8][7] = {};

    for (int k0 = 0; k0 < PMID; k0 += 8) {
        As[akc + 0][am] = aR.x;
        As[akc + 1][am] = aR.y;
        As[akc + 2][am] = aR.z;
        As[akc + 3][am] = aR.w;
        if (bAct) *(float4*)&Bs[bk][bc4] = bR;
        __syncthreads();

        if (k0 + 8 < PMID) {
            aR = *(const float4*)(w3 + (size_t)(m0 + am) * PMID + k0 + 8 + akc);
            if (bAct) bR = *(const float4*)(y2b + (size_t)(bk + k0 + 8) * HW + n0 + bc4);
        }

        #pragma unroll
        for (int k = 0; k < 8; k++) {
            float4 a0 = *(const float4*)&As[k][ty << 3];
            float4 a1 = *(const float4*)&As[k][(ty << 3) + 4];
            float ar[8] = {a0.x, a0.y, a0.z, a0.w, a1.x, a1.y, a1.z, a1.w};
            float br[7];
            #pragma unroll
            for (int j = 0; j < 7; j++) br[j] = Bs[k][tx * 7 + j];
            #pragma unroll
            for (int i = 0; i < 8; i++)
                #pragma unroll
                for (int j = 0; j < 7; j++)
                    acc[i][j] += ar[i] * br[j];
        }
        __syncthreads();
    }

    #pragma unroll
    for (int i = 0; i < 8; i++) {
        int m = m0 + (ty << 3) + i;
        const int*   pr  = perm_res + (size_t)m * HW + n0 + tx * 7;
        const float* xr  = x   + (size_t)(b * CIN + m) * HW;
        float*       dst = out + (size_t)(b * CIN + m) * HW + n0 + tx * 7;
        #pragma unroll
        for (int j = 0; j < 7; j++) {
            float r = xr[pr[j]];
            dst[j] = fmaxf(acc[i][j] + r, 0.f);
        }
    }
}

// ---------------------------------------------------------------------------
extern "C" void kernel_launch(void* const* d_in, const int* in_sizes, int n_in,
                              void* d_out, int out_size) {
    const float* x        = (const float*)d_in[0];
    const float* w1       = (const float*)d_in[1];
    const float* wd       = (const float*)d_in[2];
    const float* w3       = (const float*)d_in[3];
    const int*   perm_d   = (const int*)d_in[4];
    const int*   perm_res = (const int*)d_in[5];
    float* out = (float*)d_out;

    (void)in_sizes; (void)n_in; (void)out_size;

    k_conv1      <<<dim3(7, 2, BATCH), 256>>>(x, w1);
    k_shuffle_pad<<<BATCH * PMID, 256>>>(perm_d);
    k_conv3      <<<dim3(7, 2, BATCH), 256>>>(wd);
    k_conv1b     <<<dim3(7, 8, BATCH), 256>>>(w3, x, perm_res, out);
}

// round 4
// speedup vs baseline: 1.8022x; 1.4741x over previous
#include <cuda_runtime.h>
#include <cuda_bf16.h>
#include <cstdint>

#define BATCH 32
#define CIN   1024
#define PMID  256
#define HW    784
#define APAD  36          // smem row stride (bf16 elems) for 32-k chunks

__device__ float g_y1[BATCH * PMID * HW];
__device__ float g_y2[BATCH * PMID * HW];

// ---------------------------------------------------------------------------
__device__ __forceinline__ void split_bf(float v, uint16_t& h, uint16_t& l) {
    __nv_bfloat16 bh = __float2bfloat16(v);
    float r = v - __bfloat162float(bh);
    __nv_bfloat16 bl = __float2bfloat16(r);
    h = __bfloat16_as_ushort(bh);
    l = __bfloat16_as_ushort(bl);
}

__device__ __forceinline__ void mma_bf(float* d, const uint32_t* a,
                                       uint32_t b0, uint32_t b1) {
    asm volatile(
        "mma.sync.aligned.m16n8k16.row.col.f32.bf16.bf16.f32 "
        "{%0,%1,%2,%3}, {%4,%5,%6,%7}, {%8,%9}, {%0,%1,%2,%3};"
        : "+f"(d[0]), "+f"(d[1]), "+f"(d[2]), "+f"(d[3])
        : "r"(a[0]), "r"(a[1]), "r"(a[2]), "r"(a[3]), "r"(b0), "r"(b1));
}

// Compute one BK=32 chunk: 2 k16 steps, warp tile 32(M) x 56(N), split-bf16 x3.
__device__ __forceinline__ void compute_chunk(
    const uint16_t* __restrict__ Ah, const uint16_t* __restrict__ Al,
    const uint16_t* __restrict__ Bh, const uint16_t* __restrict__ Bl,
    float acc[2][7][4], int wm, int wn, int lane) {
    const int r0 = lane >> 2, kw = (lane & 3) << 1;
    #pragma unroll
    for (int s = 0; s < 2; s++) {
        const int kb = s * 16 + kw;
        uint32_t ah[2][4], al[2][4];
        #pragma unroll
        for (int i = 0; i < 2; i++) {
            int m = wm * 32 + i * 16 + r0;
            ah[i][0] = *(const uint32_t*)&Ah[m * APAD + kb];
            ah[i][1] = *(const uint32_t*)&Ah[(m + 8) * APAD + kb];
            ah[i][2] = *(const uint32_t*)&Ah[m * APAD + kb + 8];
            ah[i][3] = *(const uint32_t*)&Ah[(m + 8) * APAD + kb + 8];
            al[i][0] = *(const uint32_t*)&Al[m * APAD + kb];
            al[i][1] = *(const uint32_t*)&Al[(m + 8) * APAD + kb];
            al[i][2] = *(const uint32_t*)&Al[m * APAD + kb + 8];
            al[i][3] = *(const uint32_t*)&Al[(m + 8) * APAD + kb + 8];
        }
        #pragma unroll
        for (int j = 0; j < 7; j++) {
            int n = wn * 56 + j * 8 + r0;
            uint32_t bh0 = *(const uint32_t*)&Bh[n * APAD + kb];
            uint32_t bh1 = *(const uint32_t*)&Bh[n * APAD + kb + 8];
            uint32_t bl0 = *(const uint32_t*)&Bl[n * APAD + kb];
            uint32_t bl1 = *(const uint32_t*)&Bl[n * APAD + kb + 8];
            #pragma unroll
            for (int i = 0; i < 2; i++) {
                mma_bf(acc[i][j], ah[i], bh0, bh1);
                mma_bf(acc[i][j], al[i], bh0, bh1);
                mma_bf(acc[i][j], ah[i], bl0, bl1);
            }
        }
    }
}

// ---------------------------------------------------------------------------
// K1: y1 = relu(w1 @ x).  M=256, K=1024, N=784.  Tiles 128x112, BK=32.
// ---------------------------------------------------------------------------
__global__ __launch_bounds__(256) void k1(const float* __restrict__ x,
                                          const float* __restrict__ w1) {
    __shared__ uint16_t Ah[128 * APAD], Al[128 * APAD];
    __shared__ uint16_t Bh[112 * APAD], Bl[112 * APAD];
    const int b = blockIdx.z, m0 = blockIdx.y * 128, n0 = blockIdx.x * 112;
    const float* xb = x + (size_t)b * CIN * HW;
    const int tid = threadIdx.x, lane = tid & 31, warp = tid >> 5;
    const int wm = warp >> 1, wn = warp & 1;

    float4 aR[4]; float2 bR[7];
    #pragma unroll
    for (int i = 0; i < 4; i++) {
        int t = tid + i * 256;
        aR[i] = *(const float4*)(w1 + (size_t)(m0 + (t >> 3)) * CIN + ((t & 7) << 2));
    }
    #pragma unroll
    for (int i = 0; i < 7; i++) {
        int t = tid + i * 256, kc = t / 56, np = (t % 56) << 1;
        bR[i] = *(const float2*)(xb + (size_t)kc * HW + n0 + np);
    }

    float acc[2][7][4] = {};
    for (int k0 = 0; k0 < CIN; k0 += 32) {
        #pragma unroll
        for (int i = 0; i < 4; i++) {
            int t = tid + i * 256, row = t >> 3, kq = (t & 7) << 2;
            uint16_t h[4], l[4];
            split_bf(aR[i].x, h[0], l[0]); split_bf(aR[i].y, h[1], l[1]);
            split_bf(aR[i].z, h[2], l[2]); split_bf(aR[i].w, h[3], l[3]);
            *(uint32_t*)&Ah[row * APAD + kq]     = (uint32_t)h[0] | ((uint32_t)h[1] << 16);
            *(uint32_t*)&Ah[row * APAD + kq + 2] = (uint32_t)h[2] | ((uint32_t)h[3] << 16);
            *(uint32_t*)&Al[row * APAD + kq]     = (uint32_t)l[0] | ((uint32_t)l[1] << 16);
            *(uint32_t*)&Al[row * APAD + kq + 2] = (uint32_t)l[2] | ((uint32_t)l[3] << 16);
        }
        #pragma unroll
        for (int i = 0; i < 7; i++) {
            int t = tid + i * 256, kc = t / 56, np = (t % 56) << 1;
            uint16_t h0, l0, h1, l1;
            split_bf(bR[i].x, h0, l0); split_bf(bR[i].y, h1, l1);
            Bh[np * APAD + kc] = h0; Bh[(np + 1) * APAD + kc] = h1;
            Bl[np * APAD + kc] = l0; Bl[(np + 1) * APAD + kc] = l1;
        }
        __syncthreads();
        if (k0 + 32 < CIN) {
            #pragma unroll
            for (int i = 0; i < 4; i++) {
                int t = tid + i * 256;
                aR[i] = *(const float4*)(w1 + (size_t)(m0 + (t >> 3)) * CIN + k0 + 32 + ((t & 7) << 2));
            }
            #pragma unroll
            for (int i = 0; i < 7; i++) {
                int t = tid + i * 256, kc = t / 56, np = (t % 56) << 1;
                bR[i] = *(const float2*)(xb + (size_t)(k0 + 32 + kc) * HW + n0 + np);
            }
        }
        compute_chunk(Ah, Al, Bh, Bl, acc, wm, wn, lane);
        __syncthreads();
    }

    const int r0 = lane >> 2, c0l = (lane & 3) << 1;
    #pragma unroll
    for (int i = 0; i < 2; i++)
        #pragma unroll
        for (int rp = 0; rp < 2; rp++) {
            int m = m0 + wm * 32 + i * 16 + r0 + rp * 8;
            float* dst = g_y1 + (size_t)(b * PMID + m) * HW + n0;
            #pragma unroll
            for (int j = 0; j < 7; j++) {
                int col = wn * 56 + j * 8 + c0l;
                float2 v = make_float2(fmaxf(acc[i][j][rp * 2], 0.f),
                                       fmaxf(acc[i][j][rp * 2 + 1], 0.f));
                *(float2*)&dst[col] = v;
            }
        }
}

// ---------------------------------------------------------------------------
// K3: y2 = relu(conv3x3(shuffle(y1), wd)).  K = 9*256, chunks of 32 p per tap.
// ---------------------------------------------------------------------------
__global__ __launch_bounds__(256) void k3(const float* __restrict__ wd,
                                          const int* __restrict__ perm) {
    __shared__ uint16_t Ah[128 * APAD], Al[128 * APAD];
    __shared__ uint16_t Bh[112 * APAD], Bl[112 * APAD];
    const int b = blockIdx.z, q0 = blockIdx.y * 128, n0 = blockIdx.x * 112;
    const float* y1b = g_y1 + (size_t)b * PMID * HW;
    const int tid = threadIdx.x, lane = tid & 31, warp = tid >> 5;
    const int wm = warp >> 1, wn = warp & 1;

    // hoisted per-thread B-gather geometry
    int bn[14], bh0[14], bw0[14], bkc[14];
    #pragma unroll
    for (int i = 0; i < 14; i++) {
        int t = tid + i * 256;
        bkc[i] = t / 112; bn[i] = t - bkc[i] * 112;
        int hw = n0 + bn[i];
        bh0[i] = hw / 28; bw0[i] = hw % 28;
    }

    float acc[2][7][4] = {};
    for (int c = 0; c < 72; c++) {
        const int tap = c >> 3, p0 = (c & 7) << 5;
        const int dy = tap / 3 - 1, dx = tap % 3 - 1;
        #pragma unroll
        for (int i = 0; i < 16; i++) {
            int t = tid + i * 256, q = t >> 5, kc = t & 31;
            float v = wd[(size_t)(q0 + q) * (PMID * 9) + (size_t)(p0 + kc) * 9 + tap];
            uint16_t h, l; split_bf(v, h, l);
            Ah[q * APAD + kc] = h; Al[q * APAD + kc] = l;
        }
        #pragma unroll
        for (int i = 0; i < 14; i++) {
            int hh = bh0[i] + dy, ww = bw0[i] + dx;
            int p = p0 + bkc[i];
            float v = 0.f;
            if ((unsigned)hh < 28u && (unsigned)ww < 28u)
                v = y1b[(size_t)p * HW + perm[(size_t)p * HW + hh * 28 + ww]];
            uint16_t h, l; split_bf(v, h, l);
            Bh[bn[i] * APAD + bkc[i]] = h; Bl[bn[i] * APAD + bkc[i]] = l;
        }
        __syncthreads();
        compute_chunk(Ah, Al, Bh, Bl, acc, wm, wn, lane);
        __syncthreads();
    }

    const int r0 = lane >> 2, c0l = (lane & 3) << 1;
    #pragma unroll
    for (int i = 0; i < 2; i++)
        #pragma unroll
        for (int rp = 0; rp < 2; rp++) {
            int q = q0 + wm * 32 + i * 16 + r0 + rp * 8;
            float* dst = g_y2 + (size_t)(b * PMID + q) * HW + n0;
            #pragma unroll
            for (int j = 0; j < 7; j++) {
                int col = wn * 56 + j * 8 + c0l;
                float2 v = make_float2(fmaxf(acc[i][j][rp * 2], 0.f),
                                       fmaxf(acc[i][j][rp * 2 + 1], 0.f));
                *(float2*)&dst[col] = v;
            }
        }
}

// ---------------------------------------------------------------------------
// K4: out = relu(w3 @ y2 + shuffled residual).  M=1024, K=256.
// ---------------------------------------------------------------------------
__global__ __launch_bounds__(256) void k4(const float* __restrict__ w3,
                                          const float* __restrict__ x,
                                          const int* __restrict__ perm_res,
                                          float* __restrict__ out) {
    __shared__ uint16_t Ah[128 * APAD], Al[128 * APAD];
    __shared__ uint16_t Bh[112 * APAD], Bl[112 * APAD];
    const int b = blockIdx.z, m0 = blockIdx.y * 128, n0 = blockIdx.x * 112;
    const float* y2b = g_y2 + (size_t)b * PMID * HW;
    const int tid = threadIdx.x, lane = tid & 31, warp = tid >> 5;
    const int wm = warp >> 1, wn = warp & 1;

    float4 aR[4]; float2 bR[7];
    #pragma unroll
    for (int i = 0; i < 4; i++) {
        int t = tid + i * 256;
        aR[i] = *(const float4*)(w3 + (size_t)(m0 + (t >> 3)) * PMID + ((t & 7) << 2));
    }
    #pragma unroll
    for (int i = 0; i < 7; i++) {
        int t = tid + i * 256, kc = t / 56, np = (t % 56) << 1;
        bR[i] = *(const float2*)(y2b + (size_t)kc * HW + n0 + np);
    }

    float acc[2][7][4] = {};
    for (int k0 = 0; k0 < PMID; k0 += 32) {
        #pragma unroll
        for (int i = 0; i < 4; i++) {
            int t = tid + i * 256, row = t >> 3, kq = (t & 7) << 2;
            uint16_t h[4], l[4];
            split_bf(aR[i].x, h[0], l[0]); split_bf(aR[i].y, h[1], l[1]);
            split_bf(aR[i].z, h[2], l[2]); split_bf(aR[i].w, h[3], l[3]);
            *(uint32_t*)&Ah[row * APAD + kq]     = (uint32_t)h[0] | ((uint32_t)h[1] << 16);
            *(uint32_t*)&Ah[row * APAD + kq + 2] = (uint32_t)h[2] | ((uint32_t)h[3] << 16);
            *(uint32_t*)&Al[row * APAD + kq]     = (uint32_t)l[0] | ((uint32_t)l[1] << 16);
            *(uint32_t*)&Al[row * APAD + kq + 2] = (uint32_t)l[2] | ((uint32_t)l[3] << 16);
        }
        #pragma unroll
        for (int i = 0; i < 7; i++) {
            int t = tid + i * 256, kc = t / 56, np = (t % 56) << 1;
            uint16_t h0, l0, h1, l1;
            split_bf(bR[i].x, h0, l0); split_bf(bR[i].y, h1, l1);
            Bh[np * APAD + kc] = h0; Bh[(np + 1) * APAD + kc] = h1;
            Bl[np * APAD + kc] = l0; Bl[(np + 1) * APAD + kc] = l1;
        }
        __syncthreads();
        if (k0 + 32 < PMID) {
            #pragma unroll
            for (int i = 0; i < 4; i++) {
                int t = tid + i * 256;
                aR[i] = *(const float4*)(w3 + (size_t)(m0 + (t >> 3)) * PMID + k0 + 32 + ((t & 7) << 2));
            }
            #pragma unroll
            for (int i = 0; i < 7; i++) {
                int t = tid + i * 256, kc = t / 56, np = (t % 56) << 1;
                bR[i] = *(const float2*)(y2b + (size_t)(k0 + 32 + kc) * HW + n0 + np);
            }
        }
        compute_chunk(Ah, Al, Bh, Bl, acc, wm, wn, lane);
        __syncthreads();
    }

    const int r0 = lane >> 2, c0l = (lane & 3) << 1;
    #pragma unroll
    for (int i = 0; i < 2; i++)
        #pragma unroll
        for (int rp = 0; rp < 2; rp++) {
            int m = m0 + wm * 32 + i * 16 + r0 + rp * 8;
            const int*   pr  = perm_res + (size_t)m * HW + n0;
            const float* xr  = x   + (size_t)(b * CIN + m) * HW;
            float*       dst = out + (size_t)(b * CIN + m) * HW + n0;
            #pragma unroll
            for (int j = 0; j < 7; j++) {
                int col = wn * 56 + j * 8 + c0l;
                float v0 = acc[i][j][rp * 2]     + xr[pr[col]];
                float v1 = acc[i][j][rp * 2 + 1] + xr[pr[col + 1]];
                *(float2*)&dst[col] = make_float2(fmaxf(v0, 0.f), fmaxf(v1, 0.f));
            }
        }
}

// ---------------------------------------------------------------------------
extern "C" void kernel_launch(void* const* d_in, const int* in_sizes, int n_in,
                              void* d_out, int out_size) {
    const float* x        = (const float*)d_in[0];
    const float* w1       = (const float*)d_in[1];
    const float* wd       = (const float*)d_in[2];
    const float* w3       = (const float*)d_in[3];
    const int*   perm_d   = (const int*)d_in[4];
    const int*   perm_res = (const int*)d_in[5];
    float* out = (float*)d_out;
    (void)in_sizes; (void)n_in; (void)out_size;

    k1<<<dim3(7, 2, BATCH), 256>>>(x, w1);
    k3<<<dim3(7, 2, BATCH), 256>>>(wd, perm_d);
    k4<<<dim3(7, 8, BATCH), 256>>>(w3, x, perm_res, out);
}

// round 5
// speedup vs baseline: 1.9348x; 1.0736x over previous
#include <cuda_runtime.h>
#include <cuda_bf16.h>
#include <cstdint>

#define BATCH 32
#define CIN   1024
#define PMID  256
#define HW    784
#define APAD  40            // smem row stride (bf16) -> 80B, conflict-free, 16B-vector OK

// Pre-split operands (bf16 hi/lo)
__device__ uint16_t g_xh [BATCH * CIN * HW],  g_xl [BATCH * CIN * HW];
__device__ uint16_t g_w1h[PMID * CIN],        g_w1l[PMID * CIN];
__device__ uint16_t g_w3h[CIN * PMID],        g_w3l[CIN * PMID];
__device__ uint16_t g_wdh[9 * PMID * PMID],   g_wdl[9 * PMID * PMID];   // [tap][q][p]
__device__ uint16_t g_y1h[BATCH * PMID * HW], g_y1l[BATCH * PMID * HW];
__device__ uint16_t g_ysh[BATCH * PMID * 960], g_ysl[BATCH * PMID * 960]; // shuffled, padded 30x32
__device__ uint16_t g_y2h[BATCH * PMID * HW], g_y2l[BATCH * PMID * HW];

// smem layout (bf16 elems): A hi 2x5120, A lo 2x5120, B hi 2x4480, B lo 2x4480
#define ASZ 5120
#define BSZ 4480
#define OF_AH 0
#define OF_AL 10240
#define OF_BH 20480
#define OF_BL 29440
#define SMEM_BYTES (38400 * 2)

// ---------------------------------------------------------------------------
__device__ __forceinline__ void split_bf(float v, uint16_t& h, uint16_t& l) {
    __nv_bfloat16 bh = __float2bfloat16(v);
    float r = v - __bfloat162float(bh);
    h = __bfloat16_as_ushort(bh);
    l = __bfloat16_as_ushort(__float2bfloat16(r));
}
__device__ __forceinline__ uint32_t pack2(uint16_t a, uint16_t b) {
    return (uint32_t)a | ((uint32_t)b << 16);
}

__device__ __forceinline__ void mma_bf(float* d, const uint32_t* a,
                                       uint32_t b0, uint32_t b1) {
    asm volatile(
        "mma.sync.aligned.m16n8k16.row.col.f32.bf16.bf16.f32 "
        "{%0,%1,%2,%3}, {%4,%5,%6,%7}, {%8,%9}, {%0,%1,%2,%3};"
        : "+f"(d[0]), "+f"(d[1]), "+f"(d[2]), "+f"(d[3])
        : "r"(a[0]), "r"(a[1]), "r"(a[2]), "r"(a[3]), "r"(b0), "r"(b1));
}

// One BK=32 chunk, warp tile 32(M) x 56(N), split-bf16 x3 (hh + lh + hl).
__device__ __forceinline__ void compute_chunk(
    const uint16_t* __restrict__ Ah, const uint16_t* __restrict__ Al,
    const uint16_t* __restrict__ Bh, const uint16_t* __restrict__ Bl,
    float acc[2][7][4], int wm, int wn, int lane) {
    const int r0 = lane >> 2, kw = (lane & 3) << 1;
    #pragma unroll
    for (int s = 0; s < 2; s++) {
        const int kb = s * 16 + kw;
        uint32_t ah[2][4], al[2][4];
        #pragma unroll
        for (int i = 0; i < 2; i++) {
            int m = wm * 32 + i * 16 + r0;
            ah[i][0] = *(const uint32_t*)&Ah[m * APAD + kb];
            ah[i][1] = *(const uint32_t*)&Ah[(m + 8) * APAD + kb];
            ah[i][2] = *(const uint32_t*)&Ah[m * APAD + kb + 8];
            ah[i][3] = *(const uint32_t*)&Ah[(m + 8) * APAD + kb + 8];
            al[i][0] = *(const uint32_t*)&Al[m * APAD + kb];
            al[i][1] = *(const uint32_t*)&Al[(m + 8) * APAD + kb];
            al[i][2] = *(const uint32_t*)&Al[m * APAD + kb + 8];
            al[i][3] = *(const uint32_t*)&Al[(m + 8) * APAD + kb + 8];
        }
        #pragma unroll
        for (int j = 0; j < 7; j++) {
            int n = wn * 56 + j * 8 + r0;
            uint32_t bh0 = *(const uint32_t*)&Bh[n * APAD + kb];
            uint32_t bh1 = *(const uint32_t*)&Bh[n * APAD + kb + 8];
            uint32_t bl0 = *(const uint32_t*)&Bl[n * APAD + kb];
            uint32_t bl1 = *(const uint32_t*)&Bl[n * APAD + kb + 8];
            #pragma unroll
            for (int i = 0; i < 2; i++) {
                mma_bf(acc[i][j], ah[i], bh0, bh1);
                mma_bf(acc[i][j], al[i], bh0, bh1);
                mma_bf(acc[i][j], ah[i], bl0, bl1);
            }
        }
    }
}

// ---------------------------------------------------------------------------
// Prep kernels
// ---------------------------------------------------------------------------
__global__ __launch_bounds__(256) void p_split(const float* __restrict__ in,
                                               uint16_t* __restrict__ oh,
                                               uint16_t* __restrict__ ol, int n4) {
    int i = blockIdx.x * 256 + threadIdx.x;
    if (i >= n4) return;
    float4 v = ((const float4*)in)[i];
    uint16_t h0,l0,h1,l1,h2,l2,h3,l3;
    split_bf(v.x,h0,l0); split_bf(v.y,h1,l1); split_bf(v.z,h2,l2); split_bf(v.w,h3,l3);
    ((uint2*)oh)[i] = make_uint2(pack2(h0,h1), pack2(h2,h3));
    ((uint2*)ol)[i] = make_uint2(pack2(l0,l1), pack2(l2,l3));
}

__global__ __launch_bounds__(256) void p_wd(const float* __restrict__ wd) {
    int e = blockIdx.x * 256 + threadIdx.x;   // e = tap*65536 + q*256 + p
    int p = e & 255, q = (e >> 8) & 255, tap = e >> 16;
    float v = wd[q * 2304 + p * 9 + tap];
    uint16_t h, l; split_bf(v, h, l);
    g_wdh[e] = h; g_wdl[e] = l;
}

// shuffle + pad into 30x32 per (b,p)
__global__ __launch_bounds__(256) void p_shuf(const int* __restrict__ perm) {
    const int bp = blockIdx.x, p = bp & (PMID - 1);
    const uint16_t* sh = g_y1h + (size_t)bp * HW;
    const uint16_t* sl = g_y1l + (size_t)bp * HW;
    uint16_t* dh = g_ysh + (size_t)bp * 960;
    uint16_t* dl = g_ysl + (size_t)bp * 960;
    const int* pr = perm + (size_t)p * HW;
    for (int t = threadIdx.x; t < 960; t += 256) {
        int r = t >> 5, c = t & 31;
        uint16_t h = 0, l = 0;
        if (r >= 1 && r <= 28 && c >= 1 && c <= 28) {
            int j = pr[(r - 1) * 28 + (c - 1)];
            h = sh[j]; l = sl[j];
        }
        dh[t] = h; dl[t] = l;
    }
}

// ---------------------------------------------------------------------------
// K1: y1 = relu(w1 @ x). M=256, K=1024, N=784. Tiles 128x112, BK=32, dbl-buf.
// ---------------------------------------------------------------------------
__global__ __launch_bounds__(256) void k1() {
    extern __shared__ uint16_t sm[];
    const int b = blockIdx.z, m0 = blockIdx.y * 128, n0 = blockIdx.x * 112;
    const int tid = threadIdx.x, lane = tid & 31, warp = tid >> 5;
    const int wm = warp >> 1, wn = warp & 1;
    const uint16_t* xh = g_xh + (size_t)b * CIN * HW;
    const uint16_t* xl = g_xl + (size_t)b * CIN * HW;

    const int arow = tid >> 1, aseg = (tid & 1) << 4;

#define L_A(k0, s) {                                                           \
    const uint4* sh_ = (const uint4*)&g_w1h[(size_t)(m0 + arow) * CIN + (k0) + aseg]; \
    const uint4* sl_ = (const uint4*)&g_w1l[(size_t)(m0 + arow) * CIN + (k0) + aseg]; \
    uint4* dh_ = (uint4*)&sm[OF_AH + (s) * ASZ + arow * APAD + aseg];          \
    uint4* dl_ = (uint4*)&sm[OF_AL + (s) * ASZ + arow * APAD + aseg];          \
    dh_[0] = sh_[0]; dh_[1] = sh_[1]; dl_[0] = sl_[0]; dl_[1] = sl_[1]; }
#define L_B(k0, s) {                                                           \
    uint16_t* Bh_ = &sm[OF_BH + (s) * BSZ];                                    \
    uint16_t* Bl_ = &sm[OF_BL + (s) * BSZ];                                    \
    _Pragma("unroll") for (int i = 0; i < 7; i++) {                            \
        int t = tid + i * 256, kc = t / 56, np = (t % 56) << 1;                \
        uint32_t uh = *(const uint32_t*)&xh[(size_t)((k0) + kc) * HW + n0 + np]; \
        uint32_t ul = *(const uint32_t*)&xl[(size_t)((k0) + kc) * HW + n0 + np]; \
        Bh_[np * APAD + kc] = (uint16_t)uh; Bh_[(np + 1) * APAD + kc] = (uint16_t)(uh >> 16); \
        Bl_[np * APAD + kc] = (uint16_t)ul; Bl_[(np + 1) * APAD + kc] = (uint16_t)(ul >> 16); } }

    float acc[2][7][4] = {};
    L_A(0, 0); L_B(0, 0);
    __syncthreads();
    for (int c = 0; c < 32; c++) {
        const int s = c & 1;
        if (c + 1 < 32) { L_A((c + 1) * 32, s ^ 1); L_B((c + 1) * 32, s ^ 1); }
        compute_chunk(&sm[OF_AH + s * ASZ], &sm[OF_AL + s * ASZ],
                      &sm[OF_BH + s * BSZ], &sm[OF_BL + s * BSZ], acc, wm, wn, lane);
        __syncthreads();
    }
#undef L_A
#undef L_B

    const int r0 = lane >> 2, c0l = (lane & 3) << 1;
    #pragma unroll
    for (int i = 0; i < 2; i++)
        #pragma unroll
        for (int rp = 0; rp < 2; rp++) {
            int m = m0 + wm * 32 + i * 16 + r0 + rp * 8;
            size_t base = (size_t)(b * PMID + m) * HW + n0;
            #pragma unroll
            for (int j = 0; j < 7; j++) {
                int col = wn * 56 + j * 8 + c0l;
                float v0 = fmaxf(acc[i][j][rp * 2], 0.f);
                float v1 = fmaxf(acc[i][j][rp * 2 + 1], 0.f);
                uint16_t h0,l0,h1,l1; split_bf(v0,h0,l0); split_bf(v1,h1,l1);
                *(uint32_t*)&g_y1h[base + col] = pack2(h0, h1);
                *(uint32_t*)&g_y1l[base + col] = pack2(l0, l1);
            }
        }
}

// ---------------------------------------------------------------------------
// K3: y2 = relu(conv3x3(y1s, wd)). 72 chunks = 9 taps x 8 p-chunks.
// ---------------------------------------------------------------------------
__global__ __launch_bounds__(256) void k3() {
    extern __shared__ uint16_t sm[];
    const int b = blockIdx.z, q0 = blockIdx.y * 128, n0 = blockIdx.x * 112;
    const int tid = threadIdx.x, lane = tid & 31, warp = tid >> 5;
    const int wm = warp >> 1, wn = warp & 1;
    const uint16_t* ysh = g_ysh + (size_t)b * PMID * 960;
    const uint16_t* ysl = g_ysl + (size_t)b * PMID * 960;

    const int arow = tid >> 1, aseg = (tid & 1) << 4;

    int bkc[14], bn[14], bbase[14];
    #pragma unroll
    for (int i = 0; i < 14; i++) {
        int t = tid + i * 256;
        bkc[i] = t / 112; bn[i] = t - bkc[i] * 112;
        int hw = n0 + bn[i];
        bbase[i] = (hw / 28) * 32 + (hw % 28);
    }

#define L_A3(cc, s) {                                                          \
    int tap_ = (cc) >> 3, p0_ = ((cc) & 7) << 5;                               \
    const uint16_t* wh_ = g_wdh + (size_t)tap_ * 65536 + (size_t)(q0 + arow) * 256 + p0_ + aseg; \
    const uint16_t* wl_ = g_wdl + (size_t)tap_ * 65536 + (size_t)(q0 + arow) * 256 + p0_ + aseg; \
    uint4* dh_ = (uint4*)&sm[OF_AH + (s) * ASZ + arow * APAD + aseg];          \
    uint4* dl_ = (uint4*)&sm[OF_AL + (s) * ASZ + arow * APAD + aseg];          \
    dh_[0] = ((const uint4*)wh_)[0]; dh_[1] = ((const uint4*)wh_)[1];          \
    dl_[0] = ((const uint4*)wl_)[0]; dl_[1] = ((const uint4*)wl_)[1]; }
#define L_B3(cc, s) {                                                          \
    int tap_ = (cc) >> 3, p0_ = ((cc) & 7) << 5;                               \
    int dr_ = (tap_ / 3) * 32 + (tap_ % 3);                                    \
    uint16_t* Bh_ = &sm[OF_BH + (s) * BSZ];                                    \
    uint16_t* Bl_ = &sm[OF_BL + (s) * BSZ];                                    \
    _Pragma("unroll") for (int i = 0; i < 14; i++) {                           \
        size_t src = (size_t)(p0_ + bkc[i]) * 960 + bbase[i] + dr_;            \
        Bh_[bn[i] * APAD + bkc[i]] = ysh[src];                                 \
        Bl_[bn[i] * APAD + bkc[i]] = ysl[src]; } }

    float acc[2][7][4] = {};
    L_A3(0, 0); L_B3(0, 0);
    __syncthreads();
    for (int c = 0; c < 72; c++) {
        const int s = c & 1;
        if (c + 1 < 72) { L_A3(c + 1, s ^ 1); L_B3(c + 1, s ^ 1); }
        compute_chunk(&sm[OF_AH + s * ASZ], &sm[OF_AL + s * ASZ],
                      &sm[OF_BH + s * BSZ], &sm[OF_BL + s * BSZ], acc, wm, wn, lane);
        __syncthreads();
    }
#undef L_A3
#undef L_B3

    const int r0 = lane >> 2, c0l = (lane & 3) << 1;
    #pragma unroll
    for (int i = 0; i < 2; i++)
        #pragma unroll
        for (int rp = 0; rp < 2; rp++) {
            int q = q0 + wm * 32 + i * 16 + r0 + rp * 8;
            size_t base = (size_t)(b * PMID + q) * HW + n0;
            #pragma unroll
            for (int j = 0; j < 7; j++) {
                int col = wn * 56 + j * 8 + c0l;
                float v0 = fmaxf(acc[i][j][rp * 2], 0.f);
                float v1 = fmaxf(acc[i][j][rp * 2 + 1], 0.f);
                uint16_t h0,l0,h1,l1; split_bf(v0,h0,l0); split_bf(v1,h1,l1);
                *(uint32_t*)&g_y2h[base + col] = pack2(h0, h1);
                *(uint32_t*)&g_y2l[base + col] = pack2(l0, l1);
            }
        }
}

// ---------------------------------------------------------------------------
// K4: out = relu(w3 @ y2 + shuffled residual). M=1024, K=256.
// ---------------------------------------------------------------------------
__global__ __launch_bounds__(256) void k4(const float* __restrict__ x,
                                          const int* __restrict__ perm_res,
                                          float* __restrict__ out) {
    extern __shared__ uint16_t sm[];
    const int b = blockIdx.z, m0 = blockIdx.y * 128, n0 = blockIdx.x * 112;
    const int tid = threadIdx.x, lane = tid & 31, warp = tid >> 5;
    const int wm = warp >> 1, wn = warp & 1;
    const uint16_t* yh = g_y2h + (size_t)b * PMID * HW;
    const uint16_t* yl = g_y2l + (size_t)b * PMID * HW;

    const int arow = tid >> 1, aseg = (tid & 1) << 4;

#define L_A4(k0, s) {                                                          \
    const uint4* sh_ = (const uint4*)&g_w3h[(size_t)(m0 + arow) * PMID + (k0) + aseg]; \
    const uint4* sl_ = (const uint4*)&g_w3l[(size_t)(m0 + arow) * PMID + (k0) + aseg]; \
    uint4* dh_ = (uint4*)&sm[OF_AH + (s) * ASZ + arow * APAD + aseg];          \
    uint4* dl_ = (uint4*)&sm[OF_AL + (s) * ASZ + arow * APAD + aseg];          \
    dh_[0] = sh_[0]; dh_[1] = sh_[1]; dl_[0] = sl_[0]; dl_[1] = sl_[1]; }
#define L_B4(k0, s) {                                                          \
    uint16_t* Bh_ = &sm[OF_BH + (s) * BSZ];                                    \
    uint16_t* Bl_ = &sm[OF_BL + (s) * BSZ];                                    \
    _Pragma("unroll") for (int i = 0; i < 7; i++) {                            \
        int t = tid + i * 256, kc = t / 56, np = (t % 56) << 1;                \
        uint32_t uh = *(const uint32_t*)&yh[(size_t)((k0) + kc) * HW + n0 + np]; \
        uint32_t ul = *(const uint32_t*)&yl[(size_t)((k0) + kc) * HW + n0 + np]; \
        Bh_[np * APAD + kc] = (uint16_t)uh; Bh_[(np + 1) * APAD + kc] = (uint16_t)(uh >> 16); \
        Bl_[np * APAD + kc] = (uint16_t)ul; Bl_[(np + 1) * APAD + kc] = (uint16_t)(ul >> 16); } }

    float acc[2][7][4] = {};
    L_A4(0, 0); L_B4(0, 0);
    __syncthreads();
    for (int c = 0; c < 8; c++) {
        const int s = c & 1;
        if (c + 1 < 8) { L_A4((c + 1) * 32, s ^ 1); L_B4((c + 1) * 32, s ^ 1); }
        compute_chunk(&sm[OF_AH + s * ASZ], &sm[OF_AL + s * ASZ],
                      &sm[OF_BH + s * BSZ], &sm[OF_BL + s * BSZ], acc, wm, wn, lane);
        __syncthreads();
    }
#undef L_A4
#undef L_B4

    const int r0 = lane >> 2, c0l = (lane & 3) << 1;
    #pragma unroll
    for (int i = 0; i < 2; i++)
        #pragma unroll
        for (int rp = 0; rp < 2; rp++) {
            int m = m0 + wm * 32 + i * 16 + r0 + rp * 8;
            const int*   pr  = perm_res + (size_t)m * HW + n0;
            const float* xr  = x   + (size_t)(b * CIN + m) * HW;
            float*       dst = out + (size_t)(b * CIN + m) * HW + n0;
            #pragma unroll
            for (int j = 0; j < 7; j++) {
                int col = wn * 56 + j * 8 + c0l;
                float v0 = acc[i][j][rp * 2]     + xr[pr[col]];
                float v1 = acc[i][j][rp * 2 + 1] + xr[pr[col + 1]];
                *(float2*)&dst[col] = make_float2(fmaxf(v0, 0.f), fmaxf(v1, 0.f));
            }
        }
}

// ---------------------------------------------------------------------------
extern "C" void kernel_launch(void* const* d_in, const int* in_sizes, int n_in,
                              void* d_out, int out_size) {
    const float* x        = (const float*)d_in[0];
    const float* w1       = (const float*)d_in[1];
    const float* wd       = (const float*)d_in[2];
    const float* w3       = (const float*)d_in[3];
    const int*   perm_d   = (const int*)d_in[4];
    const int*   perm_res = (const int*)d_in[5];
    float* out = (float*)d_out;
    (void)in_sizes; (void)n_in; (void)out_size;

    static bool attr_done = false;
    if (!attr_done) {
        cudaFuncSetAttribute(k1, cudaFuncAttributeMaxDynamicSharedMemorySize, SMEM_BYTES);
        cudaFuncSetAttribute(k3, cudaFuncAttributeMaxDynamicSharedMemorySize, SMEM_BYTES);
        cudaFuncSetAttribute(k4, cudaFuncAttributeMaxDynamicSharedMemorySize, SMEM_BYTES);
        attr_done = true;
    }

    uint16_t *xh, *xl, *w1h, *w1l, *w3h, *w3l;
    cudaGetSymbolAddress((void**)&xh,  g_xh);  cudaGetSymbolAddress((void**)&xl,  g_xl);
    cudaGetSymbolAddress((void**)&w1h, g_w1h); cudaGetSymbolAddress((void**)&w1l, g_w1l);
    cudaGetSymbolAddress((void**)&w3h, g_w3h); cudaGetSymbolAddress((void**)&w3l, g_w3l);

    p_split<<<(BATCH * CIN * HW / 4 + 255) / 256, 256>>>(x, xh, xl, BATCH * CIN * HW / 4);
    p_split<<<(PMID * CIN / 4 + 255) / 256, 256>>>(w1, w1h, w1l, PMID * CIN / 4);
    p_split<<<(CIN * PMID / 4 + 255) / 256, 256>>>(w3, w3h, w3l, CIN * PMID / 4);
    p_wd<<<9 * 256, 256>>>(wd);

    k1<<<dim3(7, 2, BATCH), 256, SMEM_BYTES>>>();
    p_shuf<<<BATCH * PMID, 256>>>(perm_d);
    k3<<<dim3(7, 2, BATCH), 256, SMEM_BYTES>>>();
    k4<<<dim3(7, 8, BATCH), 256, SMEM_BYTES>>>(x, perm_res, out);
}

// round 8
// speedup vs baseline: 2.6952x; 1.3931x over previous
#include <cuda_runtime.h>
#include <cuda_bf16.h>
#include <cstdint>

#define BATCH 32
#define CIN   1024
#define PMID  256
#define HW    784

// Pre-split operands (bf16 hi/lo)
__device__ uint16_t g_xh [BATCH * CIN * HW],  g_xl [BATCH * CIN * HW];
__device__ uint16_t g_w1h[PMID * CIN],        g_w1l[PMID * CIN];
__device__ uint16_t g_w3h[CIN * PMID],        g_w3l[CIN * PMID];
__device__ uint16_t g_wdh[9 * PMID * PMID],   g_wdl[9 * PMID * PMID];   // [tap][q][p]
__device__ uint16_t g_y1h[BATCH * PMID * HW], g_y1l[BATCH * PMID * HW];
__device__ uint16_t g_ysh[BATCH * PMID * 960], g_ysl[BATCH * PMID * 960]; // shuffled pad 30x32
__device__ uint16_t g_y2h[BATCH * PMID * HW], g_y2l[BATCH * PMID * HW];

// SMEM (bytes): A [m128][k32+8pad] rows 80B; B [k32][n112+8pad] rows 240B
// AH: 2 x 10240 @ 0 ; AL: 2 x 10240 @ 20480 ; BH: 2 x 7680 @ 40960 ; BL @ 56320
#define OFF_AL 20480u
#define OFF_BH 40960u
#define OFF_BL 56320u
#define ASTRIDE 10240u
#define BSTRIDE 7680u
#define SMEM_BYTES 71680
// uint16-element indices of the B regions (used by k3 direct stores)
#define EBH 20480u
#define EBL 28160u
#define EBSTRIDE 3840u

// ---------------------------------------------------------------------------
__device__ __forceinline__ void split_bf(float v, uint16_t& h, uint16_t& l) {
    __nv_bfloat16 bh = __float2bfloat16(v);
    float r = v - __bfloat162float(bh);
    h = __bfloat16_as_ushort(bh);
    l = __bfloat16_as_ushort(__float2bfloat16(r));
}
__device__ __forceinline__ uint32_t pack2(uint16_t a, uint16_t b) {
    return (uint32_t)a | ((uint32_t)b << 16);
}
__device__ __forceinline__ uint32_t smem_u32(const void* p) {
    uint32_t a;
    asm("{ .reg .u64 t; cvta.to.shared.u64 t, %1; cvt.u32.u64 %0, t; }" : "=r"(a) : "l"(p));
    return a;
}
__device__ __forceinline__ void cp16(uint32_t d, const void* s) {
    asm volatile("cp.async.ca.shared.global [%0], [%1], 16;" :: "r"(d), "l"(s));
}
#define CP_COMMIT() asm volatile("cp.async.commit_group;" ::: "memory")
#define CP_WAIT0()  asm volatile("cp.async.wait_group 0;" ::: "memory")

__device__ __forceinline__ void ldm_x4(uint32_t* r, uint32_t a) {
    asm volatile("ldmatrix.sync.aligned.m8n8.x4.shared.b16 {%0,%1,%2,%3}, [%4];"
        : "=r"(r[0]), "=r"(r[1]), "=r"(r[2]), "=r"(r[3]) : "r"(a));
}
__device__ __forceinline__ void ldm_x4t(uint32_t* r, uint32_t a) {
    asm volatile("ldmatrix.sync.aligned.m8n8.x4.trans.shared.b16 {%0,%1,%2,%3}, [%4];"
        : "=r"(r[0]), "=r"(r[1]), "=r"(r[2]), "=r"(r[3]) : "r"(a));
}
__device__ __forceinline__ void ldm_x2t(uint32_t* r, uint32_t a) {
    asm volatile("ldmatrix.sync.aligned.m8n8.x2.trans.shared.b16 {%0,%1}, [%2];"
        : "=r"(r[0]), "=r"(r[1]) : "r"(a));
}
__device__ __forceinline__ void mma_bf(float* d, const uint32_t* a,
                                       uint32_t b0, uint32_t b1) {
    asm volatile(
        "mma.sync.aligned.m16n8k16.row.col.f32.bf16.bf16.f32 "
        "{%0,%1,%2,%3}, {%4,%5,%6,%7}, {%8,%9}, {%0,%1,%2,%3};"
        : "+f"(d[0]), "+f"(d[1]), "+f"(d[2]), "+f"(d[3])
        : "r"(a[0]), "r"(a[1]), "r"(a[2]), "r"(a[3]), "r"(b0), "r"(b1));
}

// One BK=32 chunk; warp tile 16(M) x 56(N); split-bf16 x3 (hh, lh, hl).
__device__ __forceinline__ void compute_chunk(
    uint32_t ah, uint32_t al, uint32_t bh, uint32_t bl,
    uint32_t aoff, uint32_t boff, uint32_t boff6, float acc[7][4]) {
    #pragma unroll
    for (int s = 0; s < 2; s++) {
        uint32_t a_h[4], a_l[4];
        ldm_x4(a_h, ah + aoff + s * 32);
        ldm_x4(a_l, al + aoff + s * 32);
        const uint32_t bstep = s * 3840;   // 16 k-rows x 240B
        uint32_t bh0[7], bh1[7], bl0[7], bl1[7];
        #pragma unroll
        for (int j2 = 0; j2 < 3; j2++) {
            uint32_t r[4];
            ldm_x4t(r, bh + boff + bstep + j2 * 32);
            bh0[2*j2] = r[0]; bh1[2*j2] = r[1]; bh0[2*j2+1] = r[2]; bh1[2*j2+1] = r[3];
            ldm_x4t(r, bl + boff + bstep + j2 * 32);
            bl0[2*j2] = r[0]; bl1[2*j2] = r[1]; bl0[2*j2+1] = r[2]; bl1[2*j2+1] = r[3];
        }
        {
            uint32_t r[2];
            ldm_x2t(r, bh + boff6 + bstep); bh0[6] = r[0]; bh1[6] = r[1];
            ldm_x2t(r, bl + boff6 + bstep); bl0[6] = r[0]; bl1[6] = r[1];
        }
        #pragma unroll
        for (int j = 0; j < 7; j++) mma_bf(acc[j], a_h, bh0[j], bh1[j]);
        #pragma unroll
        for (int j = 0; j < 7; j++) mma_bf(acc[j], a_l, bh0[j], bh1[j]);
        #pragma unroll
        for (int j = 0; j < 7; j++) mma_bf(acc[j], a_h, bl0[j], bl1[j]);
    }
}

// ---------------------------------------------------------------------------
// Prep kernels
// ---------------------------------------------------------------------------
__global__ __launch_bounds__(256) void p_split(const float* __restrict__ in,
                                               uint16_t* __restrict__ oh,
                                               uint16_t* __restrict__ ol, int n4) {
    int i = blockIdx.x * 256 + threadIdx.x;
    if (i >= n4) return;
    float4 v = ((const float4*)in)[i];
    uint16_t h0,l0,h1,l1,h2,l2,h3,l3;
    split_bf(v.x,h0,l0); split_bf(v.y,h1,l1); split_bf(v.z,h2,l2); split_bf(v.w,h3,l3);
    ((uint2*)oh)[i] = make_uint2(pack2(h0,h1), pack2(h2,h3));
    ((uint2*)ol)[i] = make_uint2(pack2(l0,l1), pack2(l2,l3));
}

__global__ __launch_bounds__(256) void p_wd(const float* __restrict__ wd) {
    int e = blockIdx.x * 256 + threadIdx.x;   // e = tap*65536 + q*256 + p
    int p = e & 255, q = (e >> 8) & 255, tap = e >> 16;
    float v = wd[q * 2304 + p * 9 + tap];
    uint16_t h, l; split_bf(v, h, l);
    g_wdh[e] = h; g_wdl[e] = l;
}

__global__ __launch_bounds__(256) void p_shuf(const int* __restrict__ perm) {
    const int bp = blockIdx.x, p = bp & (PMID - 1);
    const uint16_t* sh = g_y1h + (size_t)bp * HW;
    const uint16_t* sl = g_y1l + (size_t)bp * HW;
    uint16_t* dh = g_ysh + (size_t)bp * 960;
    uint16_t* dl = g_ysl + (size_t)bp * 960;
    const int* pr = perm + (size_t)p * HW;
    for (int t = threadIdx.x; t < 960; t += 256) {
        int r = t >> 5, c = t & 31;
        uint16_t h = 0, l = 0;
        if (r >= 1 && r <= 28 && c >= 1 && c <= 28) {
            int j = pr[(r - 1) * 28 + (c - 1)];
            h = sh[j]; l = sl[j];
        }
        dh[t] = h; dl[t] = l;
    }
}

// ---------------------------------------------------------------------------
// K1: y1 = relu(w1 @ x). M=256, K=1024, N=784. Tile 128x112, BK=32, 512 thr.
// ---------------------------------------------------------------------------
__global__ __launch_bounds__(512) void k1() {
    extern __shared__ uint16_t sm[];
    const uint32_t sb = smem_u32(sm);
    const int b = blockIdx.z, m0 = blockIdx.y * 128, n0 = blockIdx.x * 112;
    const int tid = threadIdx.x, lane = tid & 31, warp = tid >> 5;
    const int wm = warp >> 1, wn = warp & 1;
    const uint16_t* xh = g_xh + (size_t)b * CIN * HW;
    const uint16_t* xl = g_xl + (size_t)b * CIN * HW;
    const int ar = tid >> 2, ac = (tid & 3) << 3;           // A: row, 8-el seg
    const int bkc = tid / 14, bch = tid % 14;               // B: k-row, 8-el seg (tid<448)
    const uint32_t aoff  = ((wm * 16 + (lane & 15)) * 40 + ((lane >> 4) << 3)) * 2;
    const uint32_t boff  = ((lane & 15) * 120 + wn * 56 + ((lane >> 4) << 3)) * 2;
    const uint32_t boff6 = ((lane & 15) * 120 + wn * 56 + 48) * 2;

    float acc[7][4] = {};

#define K1_ISSUE(k0, st) do {                                                  \
    cp16(sb + (st) * ASTRIDE + (ar * 40 + ac) * 2,                             \
         g_w1h + (size_t)(m0 + ar) * CIN + (k0) + ac);                         \
    cp16(sb + OFF_AL + (st) * ASTRIDE + (ar * 40 + ac) * 2,                    \
         g_w1l + (size_t)(m0 + ar) * CIN + (k0) + ac);                         \
    if (tid < 448) {                                                           \
        cp16(sb + OFF_BH + (st) * BSTRIDE + (bkc * 120 + bch * 8) * 2,         \
             xh + (size_t)((k0) + bkc) * HW + n0 + bch * 8);                   \
        cp16(sb + OFF_BL + (st) * BSTRIDE + (bkc * 120 + bch * 8) * 2,         \
             xl + (size_t)((k0) + bkc) * HW + n0 + bch * 8);                   \
    }                                                                          \
    CP_COMMIT(); } while (0)

    K1_ISSUE(0, 0);
    for (int c = 0; c < 32; c++) {
        const int s = c & 1;
        CP_WAIT0(); __syncthreads();
        if (c + 1 < 32) K1_ISSUE((c + 1) * 32, s ^ 1);
        compute_chunk(sb + s * ASTRIDE, sb + OFF_AL + s * ASTRIDE,
                      sb + OFF_BH + s * BSTRIDE, sb + OFF_BL + s * BSTRIDE,
                      aoff, boff, boff6, acc);
    }
#undef K1_ISSUE

    const int r0 = lane >> 2, c2 = (lane & 3) << 1;
    #pragma unroll
    for (int j = 0; j < 7; j++) {
        int col = n0 + wn * 56 + j * 8 + c2;
        int mA = m0 + wm * 16 + r0;
        size_t iA = (size_t)(b * PMID + mA) * HW + col;
        size_t iB = (size_t)(b * PMID + mA + 8) * HW + col;
        float v0 = fmaxf(acc[j][0], 0.f), v1 = fmaxf(acc[j][1], 0.f);
        float v2 = fmaxf(acc[j][2], 0.f), v3 = fmaxf(acc[j][3], 0.f);
        uint16_t h0,l0,h1,l1,h2,l2,h3,l3;
        split_bf(v0,h0,l0); split_bf(v1,h1,l1); split_bf(v2,h2,l2); split_bf(v3,h3,l3);
        *(uint32_t*)&g_y1h[iA] = pack2(h0, h1);
        *(uint32_t*)&g_y1l[iA] = pack2(l0, l1);
        *(uint32_t*)&g_y1h[iB] = pack2(h2, h3);
        *(uint32_t*)&g_y1l[iB] = pack2(l2, l3);
    }
}

// ---------------------------------------------------------------------------
// K3: y2 = relu(conv3x3(ys, wd)). 72 chunks = 9 taps x 8 p-chunks.
// ---------------------------------------------------------------------------
__global__ __launch_bounds__(512) void k3() {
    extern __shared__ uint16_t sm[];
    const uint32_t sb = smem_u32(sm);
    const int b = blockIdx.z, q0 = blockIdx.y * 128, n0 = blockIdx.x * 112;
    const int tid = threadIdx.x, lane = tid & 31, warp = tid >> 5;
    const int wm = warp >> 1, wn = warp & 1;
    const uint16_t* ysh = g_ysh + (size_t)b * PMID * 960;
    const uint16_t* ysl = g_ysl + (size_t)b * PMID * 960;
    const int ar = tid >> 2, ac = (tid & 3) << 3;
    const uint32_t aoff  = ((wm * 16 + (lane & 15)) * 40 + ((lane >> 4) << 3)) * 2;
    const uint32_t boff  = ((lane & 15) * 120 + wn * 56 + ((lane >> 4) << 3)) * 2;
    const uint32_t boff6 = ((lane & 15) * 120 + wn * 56 + 48) * 2;

    int kc_i[7], nn_i[7], sb_i[7];
    #pragma unroll
    for (int i = 0; i < 7; i++) {
        int e = tid + i * 512;               // 3584 = 7*512 exactly
        kc_i[i] = e / 112; nn_i[i] = e % 112;
        int hw = n0 + nn_i[i];
        sb_i[i] = (hw / 28) * 32 + hw % 28;
    }

#define K3_ISSUEA(cc, st) do {                                                 \
    int tap_ = (cc) >> 3, p0_ = ((cc) & 7) << 5;                               \
    cp16(sb + (st) * ASTRIDE + (ar * 40 + ac) * 2,                             \
         g_wdh + (size_t)tap_ * 65536 + (size_t)(q0 + ar) * 256 + p0_ + ac);   \
    cp16(sb + OFF_AL + (st) * ASTRIDE + (ar * 40 + ac) * 2,                    \
         g_wdl + (size_t)tap_ * 65536 + (size_t)(q0 + ar) * 256 + p0_ + ac);   \
    CP_COMMIT(); } while (0)

    float acc[7][4] = {};
    // prologue: chunk 0
    K3_ISSUEA(0, 0);
    {
        #pragma unroll
        for (int i = 0; i < 7; i++) {
            size_t src = (size_t)kc_i[i] * 960 + sb_i[i];   // tap 0: dr=0
            sm[EBH + kc_i[i] * 120 + nn_i[i]] = ysh[src];
            sm[EBL + kc_i[i] * 120 + nn_i[i]] = ysl[src];
        }
    }
    for (int c = 0; c < 72; c++) {
        const int s = c & 1;
        CP_WAIT0(); __syncthreads();
        uint16_t vh[7], vl[7];
        if (c + 1 < 72) {
            K3_ISSUEA(c + 1, s ^ 1);
            int tap_ = (c + 1) >> 3, p0_ = ((c + 1) & 7) << 5;
            int dr = (tap_ / 3) * 32 + tap_ % 3;
            #pragma unroll
            for (int i = 0; i < 7; i++) {
                size_t src = (size_t)(p0_ + kc_i[i]) * 960 + sb_i[i] + dr;
                vh[i] = ysh[src]; vl[i] = ysl[src];
            }
        }
        compute_chunk(sb + s * ASTRIDE, sb + OFF_AL + s * ASTRIDE,
                      sb + OFF_BH + s * BSTRIDE, sb + OFF_BL + s * BSTRIDE,
                      aoff, boff, boff6, acc);
        if (c + 1 < 72) {
            const uint32_t be = (s ^ 1) * EBSTRIDE;
            #pragma unroll
            for (int i = 0; i < 7; i++) {
                sm[EBH + be + kc_i[i] * 120 + nn_i[i]] = vh[i];
                sm[EBL + be + kc_i[i] * 120 + nn_i[i]] = vl[i];
            }
        }
    }
#undef K3_ISSUEA

    const int r0 = lane >> 2, c2 = (lane & 3) << 1;
    #pragma unroll
    for (int j = 0; j < 7; j++) {
        int col = n0 + wn * 56 + j * 8 + c2;
        int qA = q0 + wm * 16 + r0;
        size_t iA = (size_t)(b * PMID + qA) * HW + col;
        size_t iB = (size_t)(b * PMID + qA + 8) * HW + col;
        float v0 = fmaxf(acc[j][0], 0.f), v1 = fmaxf(acc[j][1], 0.f);
        float v2 = fmaxf(acc[j][2], 0.f), v3 = fmaxf(acc[j][3], 0.f);
        uint16_t h0,l0,h1,l1,h2,l2,h3,l3;
        split_bf(v0,h0,l0); split_bf(v1,h1,l1); split_bf(v2,h2,l2); split_bf(v3,h3,l3);
        *(uint32_t*)&g_y2h[iA] = pack2(h0, h1);
        *(uint32_t*)&g_y2l[iA] = pack2(l0, l1);
        *(uint32_t*)&g_y2h[iB] = pack2(h2, h3);
        *(uint32_t*)&g_y2l[iB] = pack2(l2, l3);
    }
}

// ---------------------------------------------------------------------------
// K4: out = relu(w3 @ y2 + shuffled residual). M=1024, K=256.
// ---------------------------------------------------------------------------
__global__ __launch_bounds__(512) void k4(const float* __restrict__ x,
                                          const int* __restrict__ perm_res,
                                          float* __restrict__ out) {
    extern __shared__ uint16_t sm[];
    const uint32_t sb = smem_u32(sm);
    const int b = blockIdx.z, m0 = blockIdx.y * 128, n0 = blockIdx.x * 112;
    const int tid = threadIdx.x, lane = tid & 31, warp = tid >> 5;
    const int wm = warp >> 1, wn = warp & 1;
    const uint16_t* yh = g_y2h + (size_t)b * PMID * HW;
    const uint16_t* yl = g_y2l + (size_t)b * PMID * HW;
    const int ar = tid >> 2, ac = (tid & 3) << 3;
    const int bkc = tid / 14, bch = tid % 14;
    const uint32_t aoff  = ((wm * 16 + (lane & 15)) * 40 + ((lane >> 4) << 3)) * 2;
    const uint32_t boff  = ((lane & 15) * 120 + wn * 56 + ((lane >> 4) << 3)) * 2;
    const uint32_t boff6 = ((lane & 15) * 120 + wn * 56 + 48) * 2;

    float acc[7][4] = {};

#define K4_ISSUE(k0, st) do {                                                  \
    cp16(sb + (st) * ASTRIDE + (ar * 40 + ac) * 2,                             \
         g_w3h + (size_t)(m0 + ar) * PMID + (k0) + ac);                        \
    cp16(sb + OFF_AL + (st) * ASTRIDE + (ar * 40 + ac) * 2,                    \
         g_w3l + (size_t)(m0 + ar) * PMID + (k0) + ac);                        \
    if (tid < 448) {                                                           \
        cp16(sb + OFF_BH + (st) * BSTRIDE + (bkc * 120 + bch * 8) * 2,         \
             yh + (size_t)((k0) + bkc) * HW + n0 + bch * 8);                   \
        cp16(sb + OFF_BL + (st) * BSTRIDE + (bkc * 120 + bch * 8) * 2,         \
             yl + (size_t)((k0) + bkc) * HW + n0 + bch * 8);                   \
    }                                                                          \
    CP_COMMIT(); } while (0)

    K4_ISSUE(0, 0);
    for (int c = 0; c < 8; c++) {
        const int s = c & 1;
        CP_WAIT0(); __syncthreads();
        if (c + 1 < 8) K4_ISSUE((c + 1) * 32, s ^ 1);
        compute_chunk(sb + s * ASTRIDE, sb + OFF_AL + s * ASTRIDE,
                      sb + OFF_BH + s * BSTRIDE, sb + OFF_BL + s * BSTRIDE,
                      aoff, boff, boff6, acc);
    }
#undef K4_ISSUE

    const int r0 = lane >> 2, c2 = (lane & 3) << 1;
    const int mA = m0 + wm * 16 + r0, mB = mA + 8;
    const int*   prA = perm_res + (size_t)mA * HW + n0;
    const int*   prB = perm_res + (size_t)mB * HW + n0;
    const float* xrA = x + (size_t)(b * CIN + mA) * HW;
    const float* xrB = x + (size_t)(b * CIN + mB) * HW;
    float* dstA = out + (size_t)(b * CIN + mA) * HW + n0;
    float* dstB = out + (size_t)(b * CIN + mB) * HW + n0;
    #pragma unroll
    for (int j = 0; j < 7; j++) {
        int col = wn * 56 + j * 8 + c2;
        float a0 = acc[j][0] + xrA[prA[col]];
        float a1 = acc[j][1] + xrA[prA[col + 1]];
        float b0 = acc[j][2] + xrB[prB[col]];
        float b1 = acc[j][3] + xrB[prB[col + 1]];
        *(float2*)&dstA[col] = make_float2(fmaxf(a0, 0.f), fmaxf(a1, 0.f));
        *(float2*)&dstB[col] = make_float2(fmaxf(b0, 0.f), fmaxf(b1, 0.f));
    }
}

// ---------------------------------------------------------------------------
extern "C" void kernel_launch(void* const* d_in, const int* in_sizes, int n_in,
                              void* d_out, int out_size) {
    const float* x        = (const float*)d_in[0];
    const float* w1       = (const float*)d_in[1];
    const float* wd       = (const float*)d_in[2];
    const float* w3       = (const float*)d_in[3];
    const int*   perm_d   = (const int*)d_in[4];
    const int*   perm_res = (const int*)d_in[5];
    float* out = (float*)d_out;
    (void)in_sizes; (void)n_in; (void)out_size;

    static bool attr_done = false;
    if (!attr_done) {
        cudaFuncSetAttribute(k1, cudaFuncAttributeMaxDynamicSharedMemorySize, SMEM_BYTES);
        cudaFuncSetAttribute(k3, cudaFuncAttributeMaxDynamicSharedMemorySize, SMEM_BYTES);
        cudaFuncSetAttribute(k4, cudaFuncAttributeMaxDynamicSharedMemorySize, SMEM_BYTES);
        attr_done = true;
    }

    uint16_t *xh, *xl, *w1h, *w1l, *w3h, *w3l;
    cudaGetSymbolAddress((void**)&xh,  g_xh);  cudaGetSymbolAddress((void**)&xl,  g_xl);
    cudaGetSymbolAddress((void**)&w1h, g_w1h); cudaGetSymbolAddress((void**)&w1l, g_w1l);
    cudaGetSymbolAddress((void**)&w3h, g_w3h); cudaGetSymbolAddress((void**)&w3l, g_w3l);

    p_split<<<(BATCH * CIN * HW / 4 + 255) / 256, 256>>>(x, xh, xl, BATCH * CIN * HW / 4);
    p_split<<<(PMID * CIN / 4 + 255) / 256, 256>>>(w1, w1h, w1l, PMID * CIN / 4);
    p_split<<<(CIN * PMID / 4 + 255) / 256, 256>>>(w3, w3h, w3l, CIN * PMID / 4);
    p_wd<<<9 * 256, 256>>>(wd);

    k1<<<dim3(7, 2, BATCH), 512, SMEM_BYTES>>>();
    p_shuf<<<BATCH * PMID, 256>>>(perm_d);
    k3<<<dim3(7, 2, BATCH), 512, SMEM_BYTES>>>();
    k4<<<dim3(7, 8, BATCH), 512, SMEM_BYTES>>>(x, perm_res, out);
}